// round 15
// baseline (speedup 1.0000x reference)
#include <cuda_runtime.h>
#include <cuda_fp16.h>
#include <cstdint>

// ---------------------------------------------------------------------------
// Net_23905787969856 on GB300 (compute_103 => mma.sync fp16):
//  conv12: 2 CTAs/image (25/24 tiles), 288 threads (9 warps), 2 CTAs/SM.
//          conv1 = sliding-window half2 SIMT; conv2 = mma.sync fp16
//          window-permuted M-tiles; half2 epilogue + shfl 2x2 maxpool.
//  fc1:    mma.sync fp16, M128/N128, split-K=28, 3-stage cp.async pipeline.
//  fc2:    split-K reduce + bias + relu + GEMV + log_softmax fused.
// Launch order puts fc1 4th (profiler captures 4th launch).
// ---------------------------------------------------------------------------

#define BATCH 4096
#define HW 784
#define POOLHW 196
#define FEAT 12544
#define HID 128
#define KSPLIT 28
#define KCHUNK 448
#define CT 288                           // conv12 threads per CTA

__device__ __half g_h2[(size_t)BATCH * FEAT];     // [B][pos][co] NHWC-pooled
__device__ __half g_w2[64 * 296];                 // [co][t*32+ci] im2col fp16
__device__ __half g_wl1[(size_t)HID * FEAT];      // [n][k] permuted fp16
__device__ float g_fc1part[(size_t)KSPLIT * BATCH * HID];

__device__ __forceinline__ uint32_t smem_u32(const void* p) {
    uint32_t a;
    asm("{ .reg .u64 t; cvta.to.shared.u64 t, %1; cvt.u32.u64 %0, t; }"
        : "=r"(a) : "l"(p));
    return a;
}
__device__ __forceinline__ void ldm_x4(uint32_t addr, uint32_t& r0, uint32_t& r1,
                                       uint32_t& r2, uint32_t& r3) {
    asm volatile("ldmatrix.sync.aligned.m8n8.x4.shared.b16 {%0,%1,%2,%3}, [%4];"
                 : "=r"(r0), "=r"(r1), "=r"(r2), "=r"(r3) : "r"(addr));
}
__device__ __forceinline__ void mma_f16(float* c, uint32_t a0, uint32_t a1,
                                        uint32_t a2, uint32_t a3,
                                        uint32_t b0, uint32_t b1) {
    asm volatile(
        "mma.sync.aligned.m16n8k16.row.col.f32.f16.f16.f32 "
        "{%0,%1,%2,%3}, {%4,%5,%6,%7}, {%8,%9}, {%0,%1,%2,%3};"
        : "+f"(c[0]), "+f"(c[1]), "+f"(c[2]), "+f"(c[3])
        : "r"(a0), "r"(a1), "r"(a2), "r"(a3), "r"(b0), "r"(b1));
}
__device__ __forceinline__ uint32_t h2u(__half2 v) {
    return *reinterpret_cast<uint32_t*>(&v);
}
__device__ __forceinline__ __half2 u2h(uint32_t v) {
    return *reinterpret_cast<__half2*>(&v);
}
#define CP_ASYNC16(dst, src) \
    asm volatile("cp.async.cg.shared.global [%0], [%1], 16;" :: "r"(dst), "l"(src))
#define CP_COMMIT() asm volatile("cp.async.commit_group;" ::: "memory")
#define CP_WAIT0()  asm volatile("cp.async.wait_group 0;" ::: "memory")
#define CP_WAIT1()  asm volatile("cp.async.wait_group 1;" ::: "memory")

// ===========================================================================
// Prep kernels
// ===========================================================================
__global__ void prep_w2_kernel(const float* __restrict__ W2) {
    int i = blockIdx.x * 256 + threadIdx.x;
    if (i >= 64 * 296) return;
    int co = i / 296, col = i % 296;
    float w = 0.0f;
    if (col < 288) {
        int t = col / 32, ci = col % 32;
        w = W2[co * 288 + ci * 9 + t];
    }
    g_w2[i] = __float2half_rn(w);
}

// g_wl1[n][pos*64+co] = Wl1[co*196+pos][n]
__global__ __launch_bounds__(256)
void prep_wl1_kernel(const float* __restrict__ Wl1) {
    __shared__ float smw[64 * 129];
    int pos = blockIdx.x;
    int tid = threadIdx.x;
    for (int i = tid; i < 64 * 128; i += 256) {
        int co = i >> 7, n = i & 127;
        smw[co * 129 + n] = Wl1[(size_t)(co * POOLHW + pos) * HID + n];
    }
    __syncthreads();
    for (int i = tid; i < 128 * 64; i += 256) {
        int n = i >> 6, co = i & 63;
        g_wl1[(size_t)n * FEAT + pos * 64 + co] = __float2half_rn(smw[co * 129 + n]);
    }
}

// ===========================================================================
// conv12: CTA = (image, h); h=0: tiles [0,25), h=1: tiles [25,49).
// M-tile = 2x2 window block (4x4 px). 9 warps, 2 tiles/slot, 2 passes of 18.
// A plane: 18 rows (image rows 12h-1 .. 12h+16), 30 px/row, 32ch, 80B stride.
// conv1: sliding-window half2, thread = (channel pair, 2-col strip).
// ===========================================================================
#define OFF_A 0                          // 18*30*80 = 43200
#define OFF_B 43200                      // 64 * 592 = 37888
#define OFF_XS 81088                     // 20*32*4 = 2560 (fp32, masks)
#define OFF_XSH 83648                    // 20*32*4 = 2560 ((x,x) fp16)
#define OFF_W1 86208                     // 16*9 half2 = 576
#define OFF_B1 86784                     // 16 half2
#define OFF_B2 86848                     // 32 half2
#define C12_SMEM 86976
#define BROW 592

__global__ __launch_bounds__(CT, 2)
void conv12_kernel(const float* __restrict__ x,
                   const float* __restrict__ W1, const float* __restrict__ b1,
                   const float* __restrict__ b2) {
    extern __shared__ char sm[];
    uint32_t smb = smem_u32(sm);
    float* xs  = (float*)(sm + OFF_XS);     // [20][32]: image rows 12h-2..12h+17
    uint32_t* xsh = (uint32_t*)(sm + OFF_XSH);
    __half2* w1h = (__half2*)(sm + OFF_W1);
    __half2* b1h = (__half2*)(sm + OFF_B1);
    __half2* b2h = (__half2*)(sm + OFF_B2);
    int tid = threadIdx.x, wid = tid >> 5, lane = tid & 31;
    int b = blockIdx.x >> 1, h = blockIdx.x & 1;
    int base_ir = h * 12;
    int tstart = h ? 25 : 0;
    int tend = h ? 49 : 25;

    // ---- B via cp.async (overlaps conv1)
    for (int i = tid; i < 2368; i += CT)
        CP_ASYNC16(smb + OFF_B + i * 16, (const char*)g_w2 + i * 16);
    CP_COMMIT();

    // ---- xs slab (fp32 masks) + duplicated fp16 copy
    for (int i = tid; i < 640; i += CT) {
        int r = i >> 5, c = i & 31;
        int ir = base_ir + r - 2, ic = c - 2;
        float v = 0.0f;
        if (ir >= 0 && ir < 28 && ic >= 0 && ic < 28)
            v = x[(size_t)b * HW + ir * 28 + ic];
        xs[i] = v;
        xsh[i] = h2u(__float2half2_rn(v));
    }
    if (tid < 144) {
        int cp = tid / 9, k = tid % 9;
        w1h[cp * 9 + k] = __floats2half2_rn(W1[(cp * 2) * 9 + k], W1[(cp * 2 + 1) * 9 + k]);
    }
    if (tid < 16) b1h[tid] = __floats2half2_rn(b1[tid * 2], b1[tid * 2 + 1]);
    if (tid < 32) b2h[tid] = __floats2half2_rn(b2[tid * 2], b2[tid * 2 + 1]);
    __syncthreads();

    // ---- conv1 sliding window: thread = (cp, strip of 2 cols), 18 rows
    if (tid < 240) {
        int cp = tid & 15;
        int strip = tid >> 4;              // 0..14
        int ac0 = strip * 2;               // left output column (0..28)
        __half2 w1r[9];
#pragma unroll
        for (int k = 0; k < 9; k++) w1r[k] = w1h[cp * 9 + k];
        __half2 b1r = b1h[cp];
        int rmin = h ? 0 : 1;              // ir = base_ir + ar - 1 in [0,28)
        int rmax = h ? 16 : 17;
        bool c0ok = (ac0 >= 1);
        bool c1ok = (ac0 + 1 <= 28);

        uint32_t win[3][4];
#pragma unroll
        for (int r = 0; r < 2; r++)
#pragma unroll
            for (int j = 0; j < 4; j++)
                win[r][j] = xsh[r * 32 + ac0 + j];

#pragma unroll
        for (int ar = 0; ar < 18; ar++) {
#pragma unroll
            for (int j = 0; j < 4; j++)
                win[(ar + 2) % 3][j] = xsh[(ar + 2) * 32 + ac0 + j];
            __half2 s0 = b1r, s1 = b1r;
#pragma unroll
            for (int ky = 0; ky < 3; ky++)
#pragma unroll
                for (int kx = 0; kx < 3; kx++) {
                    __half2 wv = w1r[ky * 3 + kx];
                    s0 = __hfma2(wv, u2h(win[(ar + ky) % 3][kx]), s0);
                    s1 = __hfma2(wv, u2h(win[(ar + ky) % 3][kx + 1]), s1);
                }
            bool rv = (ar >= rmin) && (ar <= rmax);
            uint32_t cen0 = win[(ar + 1) % 3][1];
            uint32_t cen1 = win[(ar + 1) % 3][2];
            uint32_t o0 = (rv && c0ok && cen0 != 0u) ? h2u(__hmax2(s0, u2h(0u))) : 0u;
            uint32_t o1 = (rv && c1ok && cen1 != 0u) ? h2u(__hmax2(s1, u2h(0u))) : 0u;
            *(uint32_t*)(sm + OFF_A + (ar * 30 + ac0) * 80 + cp * 4) = o0;
            *(uint32_t*)(sm + OFF_A + (ar * 30 + ac0 + 1) * 80 + cp * 4) = o1;
        }
    }
    CP_WAIT0();
    __syncthreads();

    uint32_t bBase = smb + OFF_B + (uint32_t)(lane & 15) * BROW + ((lane >> 4) << 4);
    int rA = lane >> 2;
    int jm = rA & 3;                       // window member
    int widxA = rA >> 2;                   // 0/1
    const uint32_t z2 = 0;

    for (int p = 0; p < 2; p++) {
        int t0 = tstart + p * 18 + wid * 2;   // 9 warps x 2 tiles = 18/pass
        int nt = tend - t0; nt = nt > 2 ? 2 : nt;
        if (nt <= 0) continue;

        float acc[2][8][4];
#pragma unroll
        for (int u = 0; u < 2; u++)
#pragma unroll
            for (int g = 0; g < 8; g++)
#pragma unroll
                for (int q = 0; q < 4; q++) acc[u][g][q] = 0.0f;

        uint32_t apix[2];
#pragma unroll
        for (int u = 0; u < 2; u++) {
            int t = t0 + ((u < nt) ? u : 0);
            int br = t / 7, bc = t % 7;
            int r = lane & 15;
            int j = r & 3, widx = r >> 2;
            int wr = 2 * br + (widx & 1), wc = 2 * bc + (widx >> 1);
            int ar = 2 * wr + (j >> 1) - base_ir;   // top-left tap, local row
            int ac = 2 * wc + (j & 1);
            apix[u] = smb + OFF_A + (uint32_t)(ar * 30 + ac) * 80 + ((lane >> 4) << 4);
        }

        // ---- mainloop (interleaved form)
#pragma unroll
        for (int s = 0; s < 18; s++) {
            const int t9 = s >> 1;
            const uint32_t aoff = (uint32_t)(((t9 / 3) * 30 + (t9 % 3)) * 80 + (s & 1) * 32);
            const uint32_t kb = (uint32_t)s * 32;
            uint32_t a00, a01, a02, a03, a10, a11, a12, a13;
            ldm_x4(apix[0] + aoff, a00, a01, a02, a03);
            ldm_x4(apix[1] + aoff, a10, a11, a12, a13);
#pragma unroll
            for (int g2 = 0; g2 < 4; g2++) {
                uint32_t f0, f1, f2, f3;
                ldm_x4(bBase + (uint32_t)g2 * (16 * BROW) + kb, f0, f1, f2, f3);
                mma_f16(acc[0][2 * g2],     a00, a01, a02, a03, f0, f2);
                mma_f16(acc[0][2 * g2 + 1], a00, a01, a02, a03, f1, f3);
                mma_f16(acc[1][2 * g2],     a10, a11, a12, a13, f0, f2);
                mma_f16(acc[1][2 * g2 + 1], a10, a11, a12, a13, f1, f3);
            }
        }

        // ---- epilogue: half2 bias+mask+relu, shfl 2x2 pool, packed stores
        for (int u = 0; u < nt; u++) {
            int t = t0 + u;
            int br = t / 7, bc = t % 7;
            int wrA = 2 * br + widxA;
            int wcA = 2 * bc;
            int xsr = 2 * wrA + (jm >> 1) - base_ir + 2;
            int xcA = 2 * wcA + (jm & 1) + 2;
            bool mA = xs[xsr * 32 + xcA] != 0.0f;
            bool mB = xs[xsr * 32 + xcA + 2] != 0.0f;
            int posA = wrA * 14 + wcA;
            size_t obase = (size_t)b * FEAT;
#pragma unroll
            for (int g = 0; g < 8; g++) {
                int pi = g * 4 + (lane & 3);        // channel pair index
                __half2 bb = b2h[pi];
                __half2 tA = __hmax2(__hadd2(__floats2half2_rn(acc[u][g][0], acc[u][g][1]), bb),
                                     u2h(z2));
                __half2 tB = __hmax2(__hadd2(__floats2half2_rn(acc[u][g][2], acc[u][g][3]), bb),
                                     u2h(z2));
                uint32_t uA = mA ? h2u(tA) : 0u;
                uint32_t uB = mB ? h2u(tB) : 0u;
                uA = h2u(__hmax2(u2h(uA), u2h(__shfl_xor_sync(~0u, uA, 4))));
                uA = h2u(__hmax2(u2h(uA), u2h(__shfl_xor_sync(~0u, uA, 8))));
                uB = h2u(__hmax2(u2h(uB), u2h(__shfl_xor_sync(~0u, uB, 4))));
                uB = h2u(__hmax2(u2h(uB), u2h(__shfl_xor_sync(~0u, uB, 8))));
                if (jm == 0) {
                    int c0 = pi * 2;
                    *(uint32_t*)&g_h2[obase + (size_t)posA * 64 + c0] = uA;
                    *(uint32_t*)&g_h2[obase + (size_t)(posA + 1) * 64 + c0] = uB;
                }
            }
        }
    }
}

// ===========================================================================
// FC1: M=128,N=128 tile, split-K=28 (chunk 448 = 14 iters), 8 warps,
// 3-stage cp.async pipeline. A,B single fp16 planes. Partials out.
// ===========================================================================
#define FC1_RS 40
#define FC1_PLANE (128 * FC1_RS * 2)     // 10240
#define FC1_STAGE (2 * FC1_PLANE)        // 20480
#define FC1_SMEM (3 * FC1_STAGE)         // 61440

__global__ __launch_bounds__(256, 2)
void fc1_mma_kernel(int mtiles) {
    extern __shared__ char sm[];
    uint32_t smb = smem_u32(sm);
    int tid = threadIdx.x;
    int wid = tid >> 5, lane = tid & 31;
    int mtile = blockIdx.x % mtiles;
    int ks = blockIdx.x / mtiles;        // 0..27
    int rowBase = mtile * 128;
    int kbase = ks * KCHUNK;

    float acc[2][8][4];
#pragma unroll
    for (int mf = 0; mf < 2; mf++)
#pragma unroll
        for (int n = 0; n < 8; n++)
#pragma unroll
            for (int j = 0; j < 4; j++) acc[mf][n][j] = 0.0f;

    auto load_stage = [&](int stg, int kpos) {
        uint32_t base = smb + stg * FC1_STAGE;
#pragma unroll
        for (int j = 0; j < 4; j++) {
            int i = tid + j * 256;
            int ii = i & 511;
            int row = ii >> 2, q = ii & 3;
            uint32_t dst = base + (i < 512 ? 0 : FC1_PLANE)
                         + (uint32_t)(row * FC1_RS + q * 8) * 2;
            const __half* src = (i < 512)
                ? &g_h2[(size_t)(rowBase + row) * FEAT + kpos + q * 8]
                : &g_wl1[(size_t)row * FEAT + kpos + q * 8];
            CP_ASYNC16(dst, src);
        }
        CP_COMMIT();
    };

    int wm = wid >> 1, wn = wid & 1;
    uint32_t aOff = (uint32_t)((wm * 32 + (lane & 15)) * FC1_RS + (lane >> 4) * 8) * 2;
    uint32_t bOff = (uint32_t)((wn * 64 + (lane & 15)) * FC1_RS + (lane >> 4) * 8) * 2
                    + FC1_PLANE;

    const int NIT = KCHUNK / 32;         // 14
    load_stage(0, kbase);
    load_stage(1, kbase + 32);

    for (int it = 0; it < NIT; it++) {
        CP_WAIT1();
        __syncthreads();
        int stg_i = it % 3;
        uint32_t stg = smb + stg_i * FC1_STAGE;
#pragma unroll
        for (int kk = 0; kk < 2; kk++) {
            uint32_t kb = (uint32_t)kk * 32;
            uint32_t bfr[16];
#pragma unroll
            for (int g2 = 0; g2 < 4; g2++)
                ldm_x4(stg + bOff + (uint32_t)(g2 * 16 * FC1_RS) * 2 + kb,
                       bfr[g2 * 4], bfr[g2 * 4 + 1], bfr[g2 * 4 + 2], bfr[g2 * 4 + 3]);
#pragma unroll
            for (int mf = 0; mf < 2; mf++) {
                uint32_t a0, a1, a2, a3;
                ldm_x4(stg + aOff + (uint32_t)(mf * 16 * FC1_RS) * 2 + kb, a0, a1, a2, a3);
#pragma unroll
                for (int g2 = 0; g2 < 4; g2++) {
                    mma_f16(acc[mf][g2 * 2],     a0, a1, a2, a3, bfr[g2 * 4],     bfr[g2 * 4 + 2]);
                    mma_f16(acc[mf][g2 * 2 + 1], a0, a1, a2, a3, bfr[g2 * 4 + 1], bfr[g2 * 4 + 3]);
                }
            }
        }
        __syncthreads();
        if (it + 2 < NIT) load_stage((it + 2) % 3, kbase + (it + 2) * 32);
    }

    float* part = g_fc1part + (size_t)ks * BATCH * HID;
#pragma unroll
    for (int mf = 0; mf < 2; mf++) {
        int r0 = rowBase + wm * 32 + mf * 16 + lane / 4;
#pragma unroll
        for (int g2 = 0; g2 < 4; g2++)
#pragma unroll
            for (int jj = 0; jj < 2; jj++) {
                int n = wn * 64 + g2 * 16 + jj * 8 + (lane % 4) * 2;
                float* a = acc[mf][g2 * 2 + jj];
                part[(size_t)r0 * HID + n] = a[0];
                part[(size_t)r0 * HID + n + 1] = a[1];
                part[(size_t)(r0 + 8) * HID + n] = a[2];
                part[(size_t)(r0 + 8) * HID + n + 1] = a[3];
            }
    }
}

// ===========================================================================
// FC2: split-K reduce + bias + relu + (128->10) GEMV + log_softmax.
// ===========================================================================
__global__ __launch_bounds__(256)
void fc2_kernel(const float* __restrict__ bl1,
                const float* __restrict__ Wl2, const float* __restrict__ bl2,
                float* __restrict__ out, int B) {
    __shared__ float ws[128 * 10];
    __shared__ float bs[10];
    __shared__ float b1s[128];
    int tid = threadIdx.x;
    for (int i = tid; i < 1280; i += 256) ws[i] = Wl2[i];
    if (tid < 10) bs[tid] = bl2[tid];
    if (tid < 128) b1s[tid] = bl1[tid];
    __syncthreads();

    int w = blockIdx.x * 8 + tid / 32;
    int lane = tid % 32;
    if (w >= B) return;

    const size_t S = (size_t)BATCH * HID;
    float acc[10];
#pragma unroll
    for (int j = 0; j < 10; j++) acc[j] = 0.0f;
#pragma unroll
    for (int i = 0; i < 4; i++) {
        int kk = lane + 32 * i;
        const float* p = &g_fc1part[(size_t)w * HID + kk];
        float s = 0.0f;
#pragma unroll
        for (int k = 0; k < KSPLIT; k++) s += p[k * S];
        float hv = fmaxf(s + b1s[kk], 0.0f);
        const float* wr = &ws[kk * 10];
#pragma unroll
        for (int j = 0; j < 10; j++) acc[j] += hv * wr[j];
    }
#pragma unroll
    for (int j = 0; j < 10; j++)
#pragma unroll
        for (int off = 16; off > 0; off >>= 1)
            acc[j] += __shfl_xor_sync(0xffffffffu, acc[j], off);
    if (lane == 0) {
        float z[10];
        float mx = -1e30f;
#pragma unroll
        for (int j = 0; j < 10; j++) { z[j] = acc[j] + bs[j]; mx = fmaxf(mx, z[j]); }
        float s = 0.0f;
#pragma unroll
        for (int j = 0; j < 10; j++) s += expf(z[j] - mx);
        float l = logf(s);
#pragma unroll
        for (int j = 0; j < 10; j++) out[(size_t)w * 10 + j] = z[j] - mx - l;
    }
}

// ===========================================================================
extern "C" void kernel_launch(void* const* d_in, const int* in_sizes, int n_in,
                              void* d_out, int out_size) {
    const float* x   = (const float*)d_in[0];
    const float* W1  = (const float*)d_in[1];
    const float* b1  = (const float*)d_in[2];
    const float* W2  = (const float*)d_in[3];
    const float* b2  = (const float*)d_in[4];
    const float* Wl1 = (const float*)d_in[5];
    const float* bl1 = (const float*)d_in[6];
    const float* Wl2 = (const float*)d_in[7];
    const float* bl2 = (const float*)d_in[8];
    float* out = (float*)d_out;

    int B = in_sizes[0] / HW;   // 4096

    // launch order: fc1 is 4th (profiler captures it)
    prep_w2_kernel<<<(64 * 296 + 255) / 256, 256>>>(W2);
    prep_wl1_kernel<<<POOLHW, 256>>>(Wl1);

    cudaFuncSetAttribute(conv12_kernel,
                         cudaFuncAttributeMaxDynamicSharedMemorySize, C12_SMEM);
    conv12_kernel<<<B * 2, CT, C12_SMEM>>>(x, W1, b1, b2);

    int mtiles = B / 128;
    cudaFuncSetAttribute(fc1_mma_kernel,
                         cudaFuncAttributeMaxDynamicSharedMemorySize, FC1_SMEM);
    fc1_mma_kernel<<<mtiles * KSPLIT, 256, FC1_SMEM>>>(mtiles);

    fc2_kernel<<<(B + 7) / 8, 256>>>(bl1, Wl2, bl2, out, B);
}

// round 16
// speedup vs baseline: 1.5563x; 1.5563x over previous
#include <cuda_runtime.h>
#include <cuda_fp16.h>
#include <cstdint>

// ---------------------------------------------------------------------------
// Net_23905787969856 on GB300 (compute_103 => mma.sync fp16):
//  conv12: 2 CTAs/image (25/24 tiles), 256 threads, 2 CTAs/SM. conv1 =
//          sliding-window half2 SIMT; conv2 = mma.sync fp16 window-permuted
//          M-tiles; half2 epilogue + shfl 2x2 maxpool -> h2 fp16 NHWC-pooled.
//  fc1:    mma.sync fp16, M128/N128, split-K=28, 3-stage cp.async pipeline.
//  fc2:    split-K reduce + bias + relu + GEMV + log_softmax fused.
// (Exact R13 champion configuration, 428.1 us.)
// ---------------------------------------------------------------------------

#define BATCH 4096
#define HW 784
#define POOLHW 196
#define FEAT 12544
#define HID 128
#define KSPLIT 28
#define KCHUNK 448

__device__ __half g_h2[(size_t)BATCH * FEAT];     // [B][pos][co] NHWC-pooled
__device__ __half g_w2[64 * 296];                 // [co][t*32+ci] im2col fp16
__device__ __half g_wl1[(size_t)HID * FEAT];      // [n][k] permuted fp16
__device__ float g_fc1part[(size_t)KSPLIT * BATCH * HID];

__device__ __forceinline__ uint32_t smem_u32(const void* p) {
    uint32_t a;
    asm("{ .reg .u64 t; cvta.to.shared.u64 t, %1; cvt.u32.u64 %0, t; }"
        : "=r"(a) : "l"(p));
    return a;
}
__device__ __forceinline__ void ldm_x4(uint32_t addr, uint32_t& r0, uint32_t& r1,
                                       uint32_t& r2, uint32_t& r3) {
    asm volatile("ldmatrix.sync.aligned.m8n8.x4.shared.b16 {%0,%1,%2,%3}, [%4];"
                 : "=r"(r0), "=r"(r1), "=r"(r2), "=r"(r3) : "r"(addr));
}
__device__ __forceinline__ void mma_f16(float* c, uint32_t a0, uint32_t a1,
                                        uint32_t a2, uint32_t a3,
                                        uint32_t b0, uint32_t b1) {
    asm volatile(
        "mma.sync.aligned.m16n8k16.row.col.f32.f16.f16.f32 "
        "{%0,%1,%2,%3}, {%4,%5,%6,%7}, {%8,%9}, {%0,%1,%2,%3};"
        : "+f"(c[0]), "+f"(c[1]), "+f"(c[2]), "+f"(c[3])
        : "r"(a0), "r"(a1), "r"(a2), "r"(a3), "r"(b0), "r"(b1));
}
__device__ __forceinline__ uint32_t h2u(__half2 v) {
    return *reinterpret_cast<uint32_t*>(&v);
}
__device__ __forceinline__ __half2 u2h(uint32_t v) {
    return *reinterpret_cast<__half2*>(&v);
}
#define CP_ASYNC16(dst, src) \
    asm volatile("cp.async.cg.shared.global [%0], [%1], 16;" :: "r"(dst), "l"(src))
#define CP_COMMIT() asm volatile("cp.async.commit_group;" ::: "memory")
#define CP_WAIT0()  asm volatile("cp.async.wait_group 0;" ::: "memory")
#define CP_WAIT1()  asm volatile("cp.async.wait_group 1;" ::: "memory")

// ===========================================================================
// Prep kernels
// ===========================================================================
__global__ void prep_w2_kernel(const float* __restrict__ W2) {
    int i = blockIdx.x * 256 + threadIdx.x;
    if (i >= 64 * 296) return;
    int co = i / 296, col = i % 296;
    float w = 0.0f;
    if (col < 288) {
        int t = col / 32, ci = col % 32;
        w = W2[co * 288 + ci * 9 + t];
    }
    g_w2[i] = __float2half_rn(w);
}

// g_wl1[n][pos*64+co] = Wl1[co*196+pos][n]
__global__ __launch_bounds__(256)
void prep_wl1_kernel(const float* __restrict__ Wl1) {
    __shared__ float smw[64 * 129];
    int pos = blockIdx.x;
    int tid = threadIdx.x;
    for (int i = tid; i < 64 * 128; i += 256) {
        int co = i >> 7, n = i & 127;
        smw[co * 129 + n] = Wl1[(size_t)(co * POOLHW + pos) * HID + n];
    }
    __syncthreads();
    for (int i = tid; i < 128 * 64; i += 256) {
        int n = i >> 6, co = i & 63;
        g_wl1[(size_t)n * FEAT + pos * 64 + co] = __float2half_rn(smw[co * 129 + n]);
    }
}

// ===========================================================================
// conv12: CTA = (image, h); h=0: tiles [0,25), h=1: tiles [25,49).
// M-tile = 2x2 window block (4x4 px). 8 warps, 2 tiles per pass, n=64/warp.
// A plane: 18 rows (image rows 12h-1 .. 12h+16), 30 px/row, 32ch, 80B stride.
// conv1: sliding-window half2, thread = (channel pair, 2-col strip).
// ===========================================================================
#define OFF_A 0                          // 18*30*80 = 43200
#define OFF_B 43200                      // 64 * 592 = 37888
#define OFF_XS 81088                     // 20*32*4 = 2560 (fp32, masks)
#define OFF_XSH 83648                    // 20*32*4 = 2560 ((x,x) fp16)
#define OFF_W1 86208                     // 16*9 half2 = 576
#define OFF_B1 86784                     // 16 half2
#define OFF_B2 86848                     // 32 half2
#define C12_SMEM 86976
#define BROW 592

__global__ __launch_bounds__(256, 2)
void conv12_kernel(const float* __restrict__ x,
                   const float* __restrict__ W1, const float* __restrict__ b1,
                   const float* __restrict__ b2) {
    extern __shared__ char sm[];
    uint32_t smb = smem_u32(sm);
    float* xs  = (float*)(sm + OFF_XS);     // [20][32]: image rows 12h-2..12h+17
    uint32_t* xsh = (uint32_t*)(sm + OFF_XSH);
    __half2* w1h = (__half2*)(sm + OFF_W1);
    __half2* b1h = (__half2*)(sm + OFF_B1);
    __half2* b2h = (__half2*)(sm + OFF_B2);
    int tid = threadIdx.x, wid = tid >> 5, lane = tid & 31;
    int b = blockIdx.x >> 1, h = blockIdx.x & 1;
    int base_ir = h * 12;
    int tstart = h ? 25 : 0;
    int tend = h ? 49 : 25;

    // ---- B via cp.async (overlaps conv1)
    for (int i = tid; i < 2368; i += 256)
        CP_ASYNC16(smb + OFF_B + i * 16, (const char*)g_w2 + i * 16);
    CP_COMMIT();

    // ---- xs slab (fp32 masks) + duplicated fp16 copy
    for (int i = tid; i < 640; i += 256) {
        int r = i >> 5, c = i & 31;
        int ir = base_ir + r - 2, ic = c - 2;
        float v = 0.0f;
        if (ir >= 0 && ir < 28 && ic >= 0 && ic < 28)
            v = x[(size_t)b * HW + ir * 28 + ic];
        xs[i] = v;
        xsh[i] = h2u(__float2half2_rn(v));
    }
    if (tid < 144) {
        int cp = tid / 9, k = tid % 9;
        w1h[cp * 9 + k] = __floats2half2_rn(W1[(cp * 2) * 9 + k], W1[(cp * 2 + 1) * 9 + k]);
    }
    if (tid < 16) b1h[tid] = __floats2half2_rn(b1[tid * 2], b1[tid * 2 + 1]);
    if (tid < 32) b2h[tid] = __floats2half2_rn(b2[tid * 2], b2[tid * 2 + 1]);
    __syncthreads();

    // ---- conv1 sliding window: thread = (cp, strip of 2 cols), 18 rows
    if (tid < 240) {
        int cp = tid & 15;
        int strip = tid >> 4;              // 0..14
        int ac0 = strip * 2;               // left output column (0..28)
        __half2 w1r[9];
#pragma unroll
        for (int k = 0; k < 9; k++) w1r[k] = w1h[cp * 9 + k];
        __half2 b1r = b1h[cp];
        int rmin = h ? 0 : 1;              // ir = base_ir + ar - 1 in [0,28)
        int rmax = h ? 16 : 17;
        bool c0ok = (ac0 >= 1);
        bool c1ok = (ac0 + 1 <= 28);

        uint32_t win[3][4];
#pragma unroll
        for (int r = 0; r < 2; r++)
#pragma unroll
            for (int j = 0; j < 4; j++)
                win[r][j] = xsh[r * 32 + ac0 + j];

#pragma unroll
        for (int ar = 0; ar < 18; ar++) {
#pragma unroll
            for (int j = 0; j < 4; j++)
                win[(ar + 2) % 3][j] = xsh[(ar + 2) * 32 + ac0 + j];
            __half2 s0 = b1r, s1 = b1r;
#pragma unroll
            for (int ky = 0; ky < 3; ky++)
#pragma unroll
                for (int kx = 0; kx < 3; kx++) {
                    __half2 wv = w1r[ky * 3 + kx];
                    s0 = __hfma2(wv, u2h(win[(ar + ky) % 3][kx]), s0);
                    s1 = __hfma2(wv, u2h(win[(ar + ky) % 3][kx + 1]), s1);
                }
            bool rv = (ar >= rmin) && (ar <= rmax);
            uint32_t cen0 = win[(ar + 1) % 3][1];
            uint32_t cen1 = win[(ar + 1) % 3][2];
            uint32_t o0 = (rv && c0ok && cen0 != 0u) ? h2u(__hmax2(s0, u2h(0u))) : 0u;
            uint32_t o1 = (rv && c1ok && cen1 != 0u) ? h2u(__hmax2(s1, u2h(0u))) : 0u;
            *(uint32_t*)(sm + OFF_A + (ar * 30 + ac0) * 80 + cp * 4) = o0;
            *(uint32_t*)(sm + OFF_A + (ar * 30 + ac0 + 1) * 80 + cp * 4) = o1;
        }
    }
    CP_WAIT0();
    __syncthreads();

    uint32_t bBase = smb + OFF_B + (uint32_t)(lane & 15) * BROW + ((lane >> 4) << 4);
    int rA = lane >> 2;
    int jm = rA & 3;                       // window member
    int widxA = rA >> 2;                   // 0/1
    const uint32_t z2 = 0;

    for (int p = 0; p < 2; p++) {
        int t0 = tstart + p * 16 + wid * 2;
        int nt = tend - t0; nt = nt > 2 ? 2 : nt;
        if (nt <= 0) continue;

        float acc[2][8][4];
#pragma unroll
        for (int u = 0; u < 2; u++)
#pragma unroll
            for (int g = 0; g < 8; g++)
#pragma unroll
                for (int q = 0; q < 4; q++) acc[u][g][q] = 0.0f;

        uint32_t apix[2];
#pragma unroll
        for (int u = 0; u < 2; u++) {
            int t = t0 + ((u < nt) ? u : 0);
            int br = t / 7, bc = t % 7;
            int r = lane & 15;
            int j = r & 3, widx = r >> 2;
            int wr = 2 * br + (widx & 1), wc = 2 * bc + (widx >> 1);
            int ar = 2 * wr + (j >> 1) - base_ir;   // top-left tap, local row
            int ac = 2 * wc + (j & 1);
            apix[u] = smb + OFF_A + (uint32_t)(ar * 30 + ac) * 80 + ((lane >> 4) << 4);
        }

        // ---- mainloop (interleaved form)
#pragma unroll
        for (int s = 0; s < 18; s++) {
            const int t9 = s >> 1;
            const uint32_t aoff = (uint32_t)(((t9 / 3) * 30 + (t9 % 3)) * 80 + (s & 1) * 32);
            const uint32_t kb = (uint32_t)s * 32;
            uint32_t a00, a01, a02, a03, a10, a11, a12, a13;
            ldm_x4(apix[0] + aoff, a00, a01, a02, a03);
            ldm_x4(apix[1] + aoff, a10, a11, a12, a13);
#pragma unroll
            for (int g2 = 0; g2 < 4; g2++) {
                uint32_t f0, f1, f2, f3;
                ldm_x4(bBase + (uint32_t)g2 * (16 * BROW) + kb, f0, f1, f2, f3);
                mma_f16(acc[0][2 * g2],     a00, a01, a02, a03, f0, f2);
                mma_f16(acc[0][2 * g2 + 1], a00, a01, a02, a03, f1, f3);
                mma_f16(acc[1][2 * g2],     a10, a11, a12, a13, f0, f2);
                mma_f16(acc[1][2 * g2 + 1], a10, a11, a12, a13, f1, f3);
            }
        }

        // ---- epilogue: half2 bias+mask+relu, shfl 2x2 pool, packed stores
        for (int u = 0; u < nt; u++) {
            int t = t0 + u;
            int br = t / 7, bc = t % 7;
            int wrA = 2 * br + widxA;
            int wcA = 2 * bc;
            int xsr = 2 * wrA + (jm >> 1) - base_ir + 2;
            int xcA = 2 * wcA + (jm & 1) + 2;
            bool mA = xs[xsr * 32 + xcA] != 0.0f;
            bool mB = xs[xsr * 32 + xcA + 2] != 0.0f;
            int posA = wrA * 14 + wcA;
            size_t obase = (size_t)b * FEAT;
#pragma unroll
            for (int g = 0; g < 8; g++) {
                int pi = g * 4 + (lane & 3);        // channel pair index
                __half2 bb = b2h[pi];
                __half2 tA = __hmax2(__hadd2(__floats2half2_rn(acc[u][g][0], acc[u][g][1]), bb),
                                     u2h(z2));
                __half2 tB = __hmax2(__hadd2(__floats2half2_rn(acc[u][g][2], acc[u][g][3]), bb),
                                     u2h(z2));
                uint32_t uA = mA ? h2u(tA) : 0u;
                uint32_t uB = mB ? h2u(tB) : 0u;
                uA = h2u(__hmax2(u2h(uA), u2h(__shfl_xor_sync(~0u, uA, 4))));
                uA = h2u(__hmax2(u2h(uA), u2h(__shfl_xor_sync(~0u, uA, 8))));
                uB = h2u(__hmax2(u2h(uB), u2h(__shfl_xor_sync(~0u, uB, 4))));
                uB = h2u(__hmax2(u2h(uB), u2h(__shfl_xor_sync(~0u, uB, 8))));
                if (jm == 0) {
                    int c0 = pi * 2;
                    *(uint32_t*)&g_h2[obase + (size_t)posA * 64 + c0] = uA;
                    *(uint32_t*)&g_h2[obase + (size_t)(posA + 1) * 64 + c0] = uB;
                }
            }
        }
    }
}

// ===========================================================================
// FC1: M=128,N=128 tile, split-K=28 (chunk 448 = 14 iters), 8 warps,
// 3-stage cp.async pipeline. A,B single fp16 planes. Partials out.
// ===========================================================================
#define FC1_RS 40
#define FC1_PLANE (128 * FC1_RS * 2)     // 10240
#define FC1_STAGE (2 * FC1_PLANE)        // 20480
#define FC1_SMEM (3 * FC1_STAGE)         // 61440

__global__ __launch_bounds__(256, 2)
void fc1_mma_kernel(int mtiles) {
    extern __shared__ char sm[];
    uint32_t smb = smem_u32(sm);
    int tid = threadIdx.x;
    int wid = tid >> 5, lane = tid & 31;
    int mtile = blockIdx.x % mtiles;
    int ks = blockIdx.x / mtiles;        // 0..27
    int rowBase = mtile * 128;
    int kbase = ks * KCHUNK;

    float acc[2][8][4];
#pragma unroll
    for (int mf = 0; mf < 2; mf++)
#pragma unroll
        for (int n = 0; n < 8; n++)
#pragma unroll
            for (int j = 0; j < 4; j++) acc[mf][n][j] = 0.0f;

    auto load_stage = [&](int stg, int kpos) {
        uint32_t base = smb + stg * FC1_STAGE;
#pragma unroll
        for (int j = 0; j < 4; j++) {
            int i = tid + j * 256;
            int ii = i & 511;
            int row = ii >> 2, q = ii & 3;
            uint32_t dst = base + (i < 512 ? 0 : FC1_PLANE)
                         + (uint32_t)(row * FC1_RS + q * 8) * 2;
            const __half* src = (i < 512)
                ? &g_h2[(size_t)(rowBase + row) * FEAT + kpos + q * 8]
                : &g_wl1[(size_t)row * FEAT + kpos + q * 8];
            CP_ASYNC16(dst, src);
        }
        CP_COMMIT();
    };

    int wm = wid >> 1, wn = wid & 1;
    uint32_t aOff = (uint32_t)((wm * 32 + (lane & 15)) * FC1_RS + (lane >> 4) * 8) * 2;
    uint32_t bOff = (uint32_t)((wn * 64 + (lane & 15)) * FC1_RS + (lane >> 4) * 8) * 2
                    + FC1_PLANE;

    const int NIT = KCHUNK / 32;         // 14
    load_stage(0, kbase);
    load_stage(1, kbase + 32);

    for (int it = 0; it < NIT; it++) {
        CP_WAIT1();
        __syncthreads();
        int stg_i = it % 3;
        uint32_t stg = smb + stg_i * FC1_STAGE;
#pragma unroll
        for (int kk = 0; kk < 2; kk++) {
            uint32_t kb = (uint32_t)kk * 32;
            uint32_t bfr[16];
#pragma unroll
            for (int g2 = 0; g2 < 4; g2++)
                ldm_x4(stg + bOff + (uint32_t)(g2 * 16 * FC1_RS) * 2 + kb,
                       bfr[g2 * 4], bfr[g2 * 4 + 1], bfr[g2 * 4 + 2], bfr[g2 * 4 + 3]);
#pragma unroll
            for (int mf = 0; mf < 2; mf++) {
                uint32_t a0, a1, a2, a3;
                ldm_x4(stg + aOff + (uint32_t)(mf * 16 * FC1_RS) * 2 + kb, a0, a1, a2, a3);
#pragma unroll
                for (int g2 = 0; g2 < 4; g2++) {
                    mma_f16(acc[mf][g2 * 2],     a0, a1, a2, a3, bfr[g2 * 4],     bfr[g2 * 4 + 2]);
                    mma_f16(acc[mf][g2 * 2 + 1], a0, a1, a2, a3, bfr[g2 * 4 + 1], bfr[g2 * 4 + 3]);
                }
            }
        }
        __syncthreads();
        if (it + 2 < NIT) load_stage((it + 2) % 3, kbase + (it + 2) * 32);
    }

    float* part = g_fc1part + (size_t)ks * BATCH * HID;
#pragma unroll
    for (int mf = 0; mf < 2; mf++) {
        int r0 = rowBase + wm * 32 + mf * 16 + lane / 4;
#pragma unroll
        for (int g2 = 0; g2 < 4; g2++)
#pragma unroll
            for (int jj = 0; jj < 2; jj++) {
                int n = wn * 64 + g2 * 16 + jj * 8 + (lane % 4) * 2;
                float* a = acc[mf][g2 * 2 + jj];
                part[(size_t)r0 * HID + n] = a[0];
                part[(size_t)r0 * HID + n + 1] = a[1];
                part[(size_t)(r0 + 8) * HID + n] = a[2];
                part[(size_t)(r0 + 8) * HID + n + 1] = a[3];
            }
    }
}

// ===========================================================================
// FC2: split-K reduce + bias + relu + (128->10) GEMV + log_softmax.
// ===========================================================================
__global__ __launch_bounds__(256)
void fc2_kernel(const float* __restrict__ bl1,
                const float* __restrict__ Wl2, const float* __restrict__ bl2,
                float* __restrict__ out, int B) {
    __shared__ float ws[128 * 10];
    __shared__ float bs[10];
    __shared__ float b1s[128];
    int tid = threadIdx.x;
    for (int i = tid; i < 1280; i += 256) ws[i] = Wl2[i];
    if (tid < 10) bs[tid] = bl2[tid];
    if (tid < 128) b1s[tid] = bl1[tid];
    __syncthreads();

    int w = blockIdx.x * 8 + tid / 32;
    int lane = tid % 32;
    if (w >= B) return;

    const size_t S = (size_t)BATCH * HID;
    float acc[10];
#pragma unroll
    for (int j = 0; j < 10; j++) acc[j] = 0.0f;
#pragma unroll
    for (int i = 0; i < 4; i++) {
        int kk = lane + 32 * i;
        const float* p = &g_fc1part[(size_t)w * HID + kk];
        float s = 0.0f;
#pragma unroll
        for (int k = 0; k < KSPLIT; k++) s += p[k * S];
        float hv = fmaxf(s + b1s[kk], 0.0f);
        const float* wr = &ws[kk * 10];
#pragma unroll
        for (int j = 0; j < 10; j++) acc[j] += hv * wr[j];
    }
#pragma unroll
    for (int j = 0; j < 10; j++)
#pragma unroll
        for (int off = 16; off > 0; off >>= 1)
            acc[j] += __shfl_xor_sync(0xffffffffu, acc[j], off);
    if (lane == 0) {
        float z[10];
        float mx = -1e30f;
#pragma unroll
        for (int j = 0; j < 10; j++) { z[j] = acc[j] + bs[j]; mx = fmaxf(mx, z[j]); }
        float s = 0.0f;
#pragma unroll
        for (int j = 0; j < 10; j++) s += expf(z[j] - mx);
        float l = logf(s);
#pragma unroll
        for (int j = 0; j < 10; j++) out[(size_t)w * 10 + j] = z[j] - mx - l;
    }
}

// ===========================================================================
extern "C" void kernel_launch(void* const* d_in, const int* in_sizes, int n_in,
                              void* d_out, int out_size) {
    const float* x   = (const float*)d_in[0];
    const float* W1  = (const float*)d_in[1];
    const float* b1  = (const float*)d_in[2];
    const float* W2  = (const float*)d_in[3];
    const float* b2  = (const float*)d_in[4];
    const float* Wl1 = (const float*)d_in[5];
    const float* bl1 = (const float*)d_in[6];
    const float* Wl2 = (const float*)d_in[7];
    const float* bl2 = (const float*)d_in[8];
    float* out = (float*)d_out;

    int B = in_sizes[0] / HW;   // 4096

    prep_w2_kernel<<<(64 * 296 + 255) / 256, 256>>>(W2);
    prep_wl1_kernel<<<POOLHW, 256>>>(Wl1);

    cudaFuncSetAttribute(conv12_kernel,
                         cudaFuncAttributeMaxDynamicSharedMemorySize, C12_SMEM);
    conv12_kernel<<<B * 2, 256, C12_SMEM>>>(x, W1, b1, b2);

    int mtiles = B / 128;
    cudaFuncSetAttribute(fc1_mma_kernel,
                         cudaFuncAttributeMaxDynamicSharedMemorySize, FC1_SMEM);
    fc1_mma_kernel<<<mtiles * KSPLIT, 256, FC1_SMEM>>>(mtiles);

    fc2_kernel<<<(B + 7) / 8, 256>>>(bl1, Wl2, bl2, out, B);
}

// round 17
// speedup vs baseline: 1.5891x; 1.0211x over previous
#include <cuda_runtime.h>
#include <cuda_fp16.h>
#include <cstdint>

// ---------------------------------------------------------------------------
// Net_23905787969856 on GB300 (compute_103 => mma.sync fp16):
//  conv12: 2 CTAs/image (25/24 tiles), 256 threads, 2 CTAs/SM. conv1 =
//          sliding-window half2 SIMT; conv2 = mma.sync fp16 window-permuted
//          M-tiles; half2 epilogue + shfl 2x2 maxpool -> h2 fp16 NHWC-pooled.
//  fc1:    mma.sync fp16, M128/N128, split-K=28, 3-stage cp.async pipeline,
//          fp16 (half2-packed) partials.
//  fc2:    split-K reduce (half2) + bias + relu + GEMV + log_softmax fused.
// ---------------------------------------------------------------------------

#define BATCH 4096
#define HW 784
#define POOLHW 196
#define FEAT 12544
#define HID 128
#define KSPLIT 28
#define KCHUNK 448

__device__ __half g_h2[(size_t)BATCH * FEAT];     // [B][pos][co] NHWC-pooled
__device__ __half g_w2[64 * 296];                 // [co][t*32+ci] im2col fp16
__device__ __half g_wl1[(size_t)HID * FEAT];      // [n][k] permuted fp16
__device__ __half g_fc1part[(size_t)KSPLIT * BATCH * HID];   // fp16 partials

__device__ __forceinline__ uint32_t smem_u32(const void* p) {
    uint32_t a;
    asm("{ .reg .u64 t; cvta.to.shared.u64 t, %1; cvt.u32.u64 %0, t; }"
        : "=r"(a) : "l"(p));
    return a;
}
__device__ __forceinline__ void ldm_x4(uint32_t addr, uint32_t& r0, uint32_t& r1,
                                       uint32_t& r2, uint32_t& r3) {
    asm volatile("ldmatrix.sync.aligned.m8n8.x4.shared.b16 {%0,%1,%2,%3}, [%4];"
                 : "=r"(r0), "=r"(r1), "=r"(r2), "=r"(r3) : "r"(addr));
}
__device__ __forceinline__ void mma_f16(float* c, uint32_t a0, uint32_t a1,
                                        uint32_t a2, uint32_t a3,
                                        uint32_t b0, uint32_t b1) {
    asm volatile(
        "mma.sync.aligned.m16n8k16.row.col.f32.f16.f16.f32 "
        "{%0,%1,%2,%3}, {%4,%5,%6,%7}, {%8,%9}, {%0,%1,%2,%3};"
        : "+f"(c[0]), "+f"(c[1]), "+f"(c[2]), "+f"(c[3])
        : "r"(a0), "r"(a1), "r"(a2), "r"(a3), "r"(b0), "r"(b1));
}
__device__ __forceinline__ uint32_t h2u(__half2 v) {
    return *reinterpret_cast<uint32_t*>(&v);
}
__device__ __forceinline__ __half2 u2h(uint32_t v) {
    return *reinterpret_cast<__half2*>(&v);
}
#define CP_ASYNC16(dst, src) \
    asm volatile("cp.async.cg.shared.global [%0], [%1], 16;" :: "r"(dst), "l"(src))
#define CP_COMMIT() asm volatile("cp.async.commit_group;" ::: "memory")
#define CP_WAIT0()  asm volatile("cp.async.wait_group 0;" ::: "memory")
#define CP_WAIT1()  asm volatile("cp.async.wait_group 1;" ::: "memory")

// ===========================================================================
// Prep kernels
// ===========================================================================
__global__ void prep_w2_kernel(const float* __restrict__ W2) {
    int i = blockIdx.x * 256 + threadIdx.x;
    if (i >= 64 * 296) return;
    int co = i / 296, col = i % 296;
    float w = 0.0f;
    if (col < 288) {
        int t = col / 32, ci = col % 32;
        w = W2[co * 288 + ci * 9 + t];
    }
    g_w2[i] = __float2half_rn(w);
}

// g_wl1[n][pos*64+co] = Wl1[co*196+pos][n]
__global__ __launch_bounds__(256)
void prep_wl1_kernel(const float* __restrict__ Wl1) {
    __shared__ float smw[64 * 129];
    int pos = blockIdx.x;
    int tid = threadIdx.x;
    for (int i = tid; i < 64 * 128; i += 256) {
        int co = i >> 7, n = i & 127;
        smw[co * 129 + n] = Wl1[(size_t)(co * POOLHW + pos) * HID + n];
    }
    __syncthreads();
    for (int i = tid; i < 128 * 64; i += 256) {
        int n = i >> 6, co = i & 63;
        g_wl1[(size_t)n * FEAT + pos * 64 + co] = __float2half_rn(smw[co * 129 + n]);
    }
}

// ===========================================================================
// conv12: CTA = (image, h); h=0: tiles [0,25), h=1: tiles [25,49).
// (unchanged from 426.7us champion)
// ===========================================================================
#define OFF_A 0                          // 18*30*80 = 43200
#define OFF_B 43200                      // 64 * 592 = 37888
#define OFF_XS 81088                     // 20*32*4 = 2560 (fp32, masks)
#define OFF_XSH 83648                    // 20*32*4 = 2560 ((x,x) fp16)
#define OFF_W1 86208                     // 16*9 half2 = 576
#define OFF_B1 86784                     // 16 half2
#define OFF_B2 86848                     // 32 half2
#define C12_SMEM 86976
#define BROW 592

__global__ __launch_bounds__(256, 2)
void conv12_kernel(const float* __restrict__ x,
                   const float* __restrict__ W1, const float* __restrict__ b1,
                   const float* __restrict__ b2) {
    extern __shared__ char sm[];
    uint32_t smb = smem_u32(sm);
    float* xs  = (float*)(sm + OFF_XS);     // [20][32]: image rows 12h-2..12h+17
    uint32_t* xsh = (uint32_t*)(sm + OFF_XSH);
    __half2* w1h = (__half2*)(sm + OFF_W1);
    __half2* b1h = (__half2*)(sm + OFF_B1);
    __half2* b2h = (__half2*)(sm + OFF_B2);
    int tid = threadIdx.x, wid = tid >> 5, lane = tid & 31;
    int b = blockIdx.x >> 1, h = blockIdx.x & 1;
    int base_ir = h * 12;
    int tstart = h ? 25 : 0;
    int tend = h ? 49 : 25;

    // ---- B via cp.async (overlaps conv1)
    for (int i = tid; i < 2368; i += 256)
        CP_ASYNC16(smb + OFF_B + i * 16, (const char*)g_w2 + i * 16);
    CP_COMMIT();

    // ---- xs slab (fp32 masks) + duplicated fp16 copy
    for (int i = tid; i < 640; i += 256) {
        int r = i >> 5, c = i & 31;
        int ir = base_ir + r - 2, ic = c - 2;
        float v = 0.0f;
        if (ir >= 0 && ir < 28 && ic >= 0 && ic < 28)
            v = x[(size_t)b * HW + ir * 28 + ic];
        xs[i] = v;
        xsh[i] = h2u(__float2half2_rn(v));
    }
    if (tid < 144) {
        int cp = tid / 9, k = tid % 9;
        w1h[cp * 9 + k] = __floats2half2_rn(W1[(cp * 2) * 9 + k], W1[(cp * 2 + 1) * 9 + k]);
    }
    if (tid < 16) b1h[tid] = __floats2half2_rn(b1[tid * 2], b1[tid * 2 + 1]);
    if (tid < 32) b2h[tid] = __floats2half2_rn(b2[tid * 2], b2[tid * 2 + 1]);
    __syncthreads();

    // ---- conv1 sliding window: thread = (cp, strip of 2 cols), 18 rows
    if (tid < 240) {
        int cp = tid & 15;
        int strip = tid >> 4;              // 0..14
        int ac0 = strip * 2;               // left output column (0..28)
        __half2 w1r[9];
#pragma unroll
        for (int k = 0; k < 9; k++) w1r[k] = w1h[cp * 9 + k];
        __half2 b1r = b1h[cp];
        int rmin = h ? 0 : 1;              // ir = base_ir + ar - 1 in [0,28)
        int rmax = h ? 16 : 17;
        bool c0ok = (ac0 >= 1);
        bool c1ok = (ac0 + 1 <= 28);

        uint32_t win[3][4];
#pragma unroll
        for (int r = 0; r < 2; r++)
#pragma unroll
            for (int j = 0; j < 4; j++)
                win[r][j] = xsh[r * 32 + ac0 + j];

#pragma unroll
        for (int ar = 0; ar < 18; ar++) {
#pragma unroll
            for (int j = 0; j < 4; j++)
                win[(ar + 2) % 3][j] = xsh[(ar + 2) * 32 + ac0 + j];
            __half2 s0 = b1r, s1 = b1r;
#pragma unroll
            for (int ky = 0; ky < 3; ky++)
#pragma unroll
                for (int kx = 0; kx < 3; kx++) {
                    __half2 wv = w1r[ky * 3 + kx];
                    s0 = __hfma2(wv, u2h(win[(ar + ky) % 3][kx]), s0);
                    s1 = __hfma2(wv, u2h(win[(ar + ky) % 3][kx + 1]), s1);
                }
            bool rv = (ar >= rmin) && (ar <= rmax);
            uint32_t cen0 = win[(ar + 1) % 3][1];
            uint32_t cen1 = win[(ar + 1) % 3][2];
            uint32_t o0 = (rv && c0ok && cen0 != 0u) ? h2u(__hmax2(s0, u2h(0u))) : 0u;
            uint32_t o1 = (rv && c1ok && cen1 != 0u) ? h2u(__hmax2(s1, u2h(0u))) : 0u;
            *(uint32_t*)(sm + OFF_A + (ar * 30 + ac0) * 80 + cp * 4) = o0;
            *(uint32_t*)(sm + OFF_A + (ar * 30 + ac0 + 1) * 80 + cp * 4) = o1;
        }
    }
    CP_WAIT0();
    __syncthreads();

    uint32_t bBase = smb + OFF_B + (uint32_t)(lane & 15) * BROW + ((lane >> 4) << 4);
    int rA = lane >> 2;
    int jm = rA & 3;                       // window member
    int widxA = rA >> 2;                   // 0/1
    const uint32_t z2 = 0;

    for (int p = 0; p < 2; p++) {
        int t0 = tstart + p * 16 + wid * 2;
        int nt = tend - t0; nt = nt > 2 ? 2 : nt;
        if (nt <= 0) continue;

        float acc[2][8][4];
#pragma unroll
        for (int u = 0; u < 2; u++)
#pragma unroll
            for (int g = 0; g < 8; g++)
#pragma unroll
                for (int q = 0; q < 4; q++) acc[u][g][q] = 0.0f;

        uint32_t apix[2];
#pragma unroll
        for (int u = 0; u < 2; u++) {
            int t = t0 + ((u < nt) ? u : 0);
            int br = t / 7, bc = t % 7;
            int r = lane & 15;
            int j = r & 3, widx = r >> 2;
            int wr = 2 * br + (widx & 1), wc = 2 * bc + (widx >> 1);
            int ar = 2 * wr + (j >> 1) - base_ir;   // top-left tap, local row
            int ac = 2 * wc + (j & 1);
            apix[u] = smb + OFF_A + (uint32_t)(ar * 30 + ac) * 80 + ((lane >> 4) << 4);
        }

        // ---- mainloop (interleaved form)
#pragma unroll
        for (int s = 0; s < 18; s++) {
            const int t9 = s >> 1;
            const uint32_t aoff = (uint32_t)(((t9 / 3) * 30 + (t9 % 3)) * 80 + (s & 1) * 32);
            const uint32_t kb = (uint32_t)s * 32;
            uint32_t a00, a01, a02, a03, a10, a11, a12, a13;
            ldm_x4(apix[0] + aoff, a00, a01, a02, a03);
            ldm_x4(apix[1] + aoff, a10, a11, a12, a13);
#pragma unroll
            for (int g2 = 0; g2 < 4; g2++) {
                uint32_t f0, f1, f2, f3;
                ldm_x4(bBase + (uint32_t)g2 * (16 * BROW) + kb, f0, f1, f2, f3);
                mma_f16(acc[0][2 * g2],     a00, a01, a02, a03, f0, f2);
                mma_f16(acc[0][2 * g2 + 1], a00, a01, a02, a03, f1, f3);
                mma_f16(acc[1][2 * g2],     a10, a11, a12, a13, f0, f2);
                mma_f16(acc[1][2 * g2 + 1], a10, a11, a12, a13, f1, f3);
            }
        }

        // ---- epilogue: half2 bias+mask+relu, shfl 2x2 pool, packed stores
        for (int u = 0; u < nt; u++) {
            int t = t0 + u;
            int br = t / 7, bc = t % 7;
            int wrA = 2 * br + widxA;
            int wcA = 2 * bc;
            int xsr = 2 * wrA + (jm >> 1) - base_ir + 2;
            int xcA = 2 * wcA + (jm & 1) + 2;
            bool mA = xs[xsr * 32 + xcA] != 0.0f;
            bool mB = xs[xsr * 32 + xcA + 2] != 0.0f;
            int posA = wrA * 14 + wcA;
            size_t obase = (size_t)b * FEAT;
#pragma unroll
            for (int g = 0; g < 8; g++) {
                int pi = g * 4 + (lane & 3);        // channel pair index
                __half2 bb = b2h[pi];
                __half2 tA = __hmax2(__hadd2(__floats2half2_rn(acc[u][g][0], acc[u][g][1]), bb),
                                     u2h(z2));
                __half2 tB = __hmax2(__hadd2(__floats2half2_rn(acc[u][g][2], acc[u][g][3]), bb),
                                     u2h(z2));
                uint32_t uA = mA ? h2u(tA) : 0u;
                uint32_t uB = mB ? h2u(tB) : 0u;
                uA = h2u(__hmax2(u2h(uA), u2h(__shfl_xor_sync(~0u, uA, 4))));
                uA = h2u(__hmax2(u2h(uA), u2h(__shfl_xor_sync(~0u, uA, 8))));
                uB = h2u(__hmax2(u2h(uB), u2h(__shfl_xor_sync(~0u, uB, 4))));
                uB = h2u(__hmax2(u2h(uB), u2h(__shfl_xor_sync(~0u, uB, 8))));
                if (jm == 0) {
                    int c0 = pi * 2;
                    *(uint32_t*)&g_h2[obase + (size_t)posA * 64 + c0] = uA;
                    *(uint32_t*)&g_h2[obase + (size_t)(posA + 1) * 64 + c0] = uB;
                }
            }
        }
    }
}

// ===========================================================================
// FC1: M=128,N=128 tile, split-K=28 (chunk 448 = 14 iters), 8 warps,
// 3-stage cp.async pipeline. fp16 half2-packed partials out.
// ===========================================================================
#define FC1_RS 40
#define FC1_PLANE (128 * FC1_RS * 2)     // 10240
#define FC1_STAGE (2 * FC1_PLANE)        // 20480
#define FC1_SMEM (3 * FC1_STAGE)         // 61440

__global__ __launch_bounds__(256, 2)
void fc1_mma_kernel(int mtiles) {
    extern __shared__ char sm[];
    uint32_t smb = smem_u32(sm);
    int tid = threadIdx.x;
    int wid = tid >> 5, lane = tid & 31;
    int mtile = blockIdx.x % mtiles;
    int ks = blockIdx.x / mtiles;        // 0..27
    int rowBase = mtile * 128;
    int kbase = ks * KCHUNK;

    float acc[2][8][4];
#pragma unroll
    for (int mf = 0; mf < 2; mf++)
#pragma unroll
        for (int n = 0; n < 8; n++)
#pragma unroll
            for (int j = 0; j < 4; j++) acc[mf][n][j] = 0.0f;

    auto load_stage = [&](int stg, int kpos) {
        uint32_t base = smb + stg * FC1_STAGE;
#pragma unroll
        for (int j = 0; j < 4; j++) {
            int i = tid + j * 256;
            int ii = i & 511;
            int row = ii >> 2, q = ii & 3;
            uint32_t dst = base + (i < 512 ? 0 : FC1_PLANE)
                         + (uint32_t)(row * FC1_RS + q * 8) * 2;
            const __half* src = (i < 512)
                ? &g_h2[(size_t)(rowBase + row) * FEAT + kpos + q * 8]
                : &g_wl1[(size_t)row * FEAT + kpos + q * 8];
            CP_ASYNC16(dst, src);
        }
        CP_COMMIT();
    };

    int wm = wid >> 1, wn = wid & 1;
    uint32_t aOff = (uint32_t)((wm * 32 + (lane & 15)) * FC1_RS + (lane >> 4) * 8) * 2;
    uint32_t bOff = (uint32_t)((wn * 64 + (lane & 15)) * FC1_RS + (lane >> 4) * 8) * 2
                    + FC1_PLANE;

    const int NIT = KCHUNK / 32;         // 14
    load_stage(0, kbase);
    load_stage(1, kbase + 32);

    for (int it = 0; it < NIT; it++) {
        CP_WAIT1();
        __syncthreads();
        int stg_i = it % 3;
        uint32_t stg = smb + stg_i * FC1_STAGE;
#pragma unroll
        for (int kk = 0; kk < 2; kk++) {
            uint32_t kb = (uint32_t)kk * 32;
            uint32_t bfr[16];
#pragma unroll
            for (int g2 = 0; g2 < 4; g2++)
                ldm_x4(stg + bOff + (uint32_t)(g2 * 16 * FC1_RS) * 2 + kb,
                       bfr[g2 * 4], bfr[g2 * 4 + 1], bfr[g2 * 4 + 2], bfr[g2 * 4 + 3]);
#pragma unroll
            for (int mf = 0; mf < 2; mf++) {
                uint32_t a0, a1, a2, a3;
                ldm_x4(stg + aOff + (uint32_t)(mf * 16 * FC1_RS) * 2 + kb, a0, a1, a2, a3);
#pragma unroll
                for (int g2 = 0; g2 < 4; g2++) {
                    mma_f16(acc[mf][g2 * 2],     a0, a1, a2, a3, bfr[g2 * 4],     bfr[g2 * 4 + 2]);
                    mma_f16(acc[mf][g2 * 2 + 1], a0, a1, a2, a3, bfr[g2 * 4 + 1], bfr[g2 * 4 + 3]);
                }
            }
        }
        __syncthreads();
        if (it + 2 < NIT) load_stage((it + 2) % 3, kbase + (it + 2) * 32);
    }

    // ---- fp16 half2-packed partial store (channels n, n+1 adjacent)
    __half* part = g_fc1part + (size_t)ks * BATCH * HID;
#pragma unroll
    for (int mf = 0; mf < 2; mf++) {
        int r0 = rowBase + wm * 32 + mf * 16 + lane / 4;
#pragma unroll
        for (int g2 = 0; g2 < 4; g2++)
#pragma unroll
            for (int jj = 0; jj < 2; jj++) {
                int n = wn * 64 + g2 * 16 + jj * 8 + (lane % 4) * 2;
                float* a = acc[mf][g2 * 2 + jj];
                *(uint32_t*)&part[(size_t)r0 * HID + n] =
                    h2u(__floats2half2_rn(a[0], a[1]));
                *(uint32_t*)&part[(size_t)(r0 + 8) * HID + n] =
                    h2u(__floats2half2_rn(a[2], a[3]));
            }
    }
}

// ===========================================================================
// FC2: split-K reduce (half2) + bias + relu + (128->10) GEMV + log_softmax.
// Lane handles channel pairs p = lane + 32*i (i=0,1), channels 2p, 2p+1.
// ===========================================================================
__global__ __launch_bounds__(256)
void fc2_kernel(const float* __restrict__ bl1,
                const float* __restrict__ Wl2, const float* __restrict__ bl2,
                float* __restrict__ out, int B) {
    __shared__ float ws[128 * 10];
    __shared__ float bs[10];
    __shared__ float b1s[128];
    int tid = threadIdx.x;
    for (int i = tid; i < 1280; i += 256) ws[i] = Wl2[i];
    if (tid < 10) bs[tid] = bl2[tid];
    if (tid < 128) b1s[tid] = bl1[tid];
    __syncthreads();

    int w = blockIdx.x * 8 + tid / 32;
    int lane = tid % 32;
    if (w >= B) return;

    const size_t S = (size_t)BATCH * HID;
    float acc[10];
#pragma unroll
    for (int j = 0; j < 10; j++) acc[j] = 0.0f;
#pragma unroll
    for (int i = 0; i < 2; i++) {
        int pp = lane + 32 * i;            // channel pair 0..63
        const __half* p = &g_fc1part[(size_t)w * HID + pp * 2];
        float s0 = 0.0f, s1 = 0.0f;
#pragma unroll
        for (int k = 0; k < KSPLIT; k++) {
            float2 f = __half22float2(*(const __half2*)&p[k * S]);
            s0 += f.x; s1 += f.y;
        }
        float hv0 = fmaxf(s0 + b1s[pp * 2], 0.0f);
        float hv1 = fmaxf(s1 + b1s[pp * 2 + 1], 0.0f);
        const float* wr0 = &ws[(pp * 2) * 10];
        const float* wr1 = &ws[(pp * 2 + 1) * 10];
#pragma unroll
        for (int j = 0; j < 10; j++) acc[j] += hv0 * wr0[j] + hv1 * wr1[j];
    }
#pragma unroll
    for (int j = 0; j < 10; j++)
#pragma unroll
        for (int off = 16; off > 0; off >>= 1)
            acc[j] += __shfl_xor_sync(0xffffffffu, acc[j], off);
    if (lane == 0) {
        float z[10];
        float mx = -1e30f;
#pragma unroll
        for (int j = 0; j < 10; j++) { z[j] = acc[j] + bs[j]; mx = fmaxf(mx, z[j]); }
        float s = 0.0f;
#pragma unroll
        for (int j = 0; j < 10; j++) s += expf(z[j] - mx);
        float l = logf(s);
#pragma unroll
        for (int j = 0; j < 10; j++) out[(size_t)w * 10 + j] = z[j] - mx - l;
    }
}

// ===========================================================================
extern "C" void kernel_launch(void* const* d_in, const int* in_sizes, int n_in,
                              void* d_out, int out_size) {
    const float* x   = (const float*)d_in[0];
    const float* W1  = (const float*)d_in[1];
    const float* b1  = (const float*)d_in[2];
    const float* W2  = (const float*)d_in[3];
    const float* b2  = (const float*)d_in[4];
    const float* Wl1 = (const float*)d_in[5];
    const float* bl1 = (const float*)d_in[6];
    const float* Wl2 = (const float*)d_in[7];
    const float* bl2 = (const float*)d_in[8];
    float* out = (float*)d_out;

    int B = in_sizes[0] / HW;   // 4096

    prep_w2_kernel<<<(64 * 296 + 255) / 256, 256>>>(W2);
    prep_wl1_kernel<<<POOLHW, 256>>>(Wl1);

    cudaFuncSetAttribute(conv12_kernel,
                         cudaFuncAttributeMaxDynamicSharedMemorySize, C12_SMEM);
    conv12_kernel<<<B * 2, 256, C12_SMEM>>>(x, W1, b1, b2);

    int mtiles = B / 128;
    cudaFuncSetAttribute(fc1_mma_kernel,
                         cudaFuncAttributeMaxDynamicSharedMemorySize, FC1_SMEM);
    fc1_mma_kernel<<<mtiles * KSPLIT, 256, FC1_SMEM>>>(mtiles);

    fc2_kernel<<<(B + 7) / 8, 256>>>(bl1, Wl2, bl2, out, B);
}